// round 1
// baseline (speedup 1.0000x reference)
#include <cuda_runtime.h>

// Problem constants
#define S      2785
#define S16    (S * 16)
#define G      689
#define BATCH  8192
#define NC     512            // batch chunks of 16
#define CAP    192            // max nnz per output column (binomial(2785,0.02): mean ~56)
#define NLAY   7              // layer 0 + 6 scan layers
#define XS_STRIDE 20          // padded floats per slot in smem (bank spread)

// ---------------- device global scratch (allocation-free rule) ----------------
__device__ float g_bufA[(size_t)NC * S16];   // 91.3 MB
__device__ float g_bufB[(size_t)NC * S16];   // 91.3 MB (pre-BN Y, always)
__device__ float g_bufC[(size_t)NC * S16];   // 91.3 MB
__device__ int2  g_ent[(size_t)NLAY * S * CAP]; // {byte_offset = i*80, w}
__device__ int   g_cnt[NLAY * S];

__device__ __forceinline__ float* getbuf(int s) {
    return s == 0 ? g_bufA : (s == 1 ? g_bufB : g_bufC);
}

// ---------------- build sparse column structure (deterministic, row order) ----
__global__ void build_kernel(const float* __restrict__ lm0, const float* __restrict__ W0,
                             const float* __restrict__ lm,  const float* __restrict__ Wl) {
    int l = blockIdx.y;
    int j = blockIdx.x * 128 + threadIdx.x;
    if (j >= S) return;
    const float* M; const float* Wm; int rows;
    if (l == 0) { M = lm0; Wm = W0; rows = G; }
    else {
        size_t off = (size_t)(l - 1) * S * S;
        M = lm + off; Wm = Wl + off; rows = S;
    }
    int2* ep = g_ent + ((size_t)l * S + j) * CAP;
    int cnt = 0;
    #pragma unroll 4
    for (int i = 0; i < rows; i++) {
        float m = M[(size_t)i * S + j];
        if (m != 0.f) {
            float w = Wm[(size_t)i * S + j];
            if (cnt < CAP) ep[cnt] = make_int2(i * (XS_STRIDE * 4), __float_as_int(w));
            cnt++;
        }
    }
    g_cnt[l * S + j] = min(cnt, CAP);
}

// ---------------- transpose x [B,G] -> tiled [NC][G][16] into bufA -----------
__global__ void xt_kernel(const float* __restrict__ x) {
    int o = blockIdx.x * blockDim.x + threadIdx.x;
    if (o >= NC * G * 16) return;
    int lane = o & 15;
    int rest = o >> 4;
    int i = rest % G;
    int c = rest / G;
    g_bufA[o] = x[(size_t)(c * 16 + lane) * G + i];
}

// ---------------- sparse SpMM: Y[c][j][0..15] = bias[j] + sum_k w * X[c][i_k][0..15]
__global__ __launch_bounds__(1024, 1)
void spmm_kernel(int in_sel, const float* __restrict__ bias, int layer, int n_slots) {
    extern __shared__ float xs[];
    const float* Xin = getbuf(in_sel);
    int c = blockIdx.x;

    // Load this chunk's full activation tile into smem (stride-padded)
    const float4* src = (const float4*)(Xin + (size_t)c * n_slots * 16);
    int n4 = n_slots * 4;
    for (int t = threadIdx.x; t < n4; t += blockDim.x) {
        int slot = t >> 2, q = t & 3;
        *(float4*)&xs[slot * XS_STRIDE + q * 4] = src[t];
    }
    __syncthreads();

    int lane4 = threadIdx.x & 3;      // which float4 of the 16 batch lanes
    int grp   = threadIdx.x >> 2;     // j-group 0..255
    const char* xsb = (const char*)xs + lane4 * 16;
    float* yb = g_bufB + (size_t)c * S16;

    for (int j = grp; j < S; j += 256) {
        int n = g_cnt[layer * S + j];
        const int2* ep = g_ent + ((size_t)layer * S + j) * CAP;
        float bj = bias[j];
        float4 acc = make_float4(bj, bj, bj, bj);
        #pragma unroll 4
        for (int k = 0; k < n; k++) {
            int2 e = ep[k];                               // {byte off, w}
            float4 xv = *(const float4*)(xsb + e.x);      // smem gather
            float w = __int_as_float(e.y);
            acc.x = fmaf(w, xv.x, acc.x);
            acc.y = fmaf(w, xv.y, acc.y);
            acc.z = fmaf(w, xv.z, acc.z);
            acc.w = fmaf(w, xv.w, acc.w);
        }
        *(float4*)(yb + j * 16 + lane4 * 4) = acc;
    }
}

// ---------------- BatchNorm (training stats) + tanh + diagonal skip ----------
__global__ __launch_bounds__(512)
void bn_kernel(int skip_sel, int out_sel,
               const float* __restrict__ gamma, const float* __restrict__ beta,
               const float* __restrict__ dvec, int has_skip) {
    int j = blockIdx.x;
    int t = threadIdx.x;
    const float* base = g_bufB + (size_t)j * 16;

    float v[16];
    float s = 0.f, ss = 0.f;
    #pragma unroll
    for (int r = 0; r < 16; r++) {
        int e = r * 512 + t;
        int c = e >> 4, lane = e & 15;
        float xv = base[(size_t)c * S16 + lane];
        v[r] = xv; s += xv; ss += xv * xv;
    }
    // deterministic block reduction
    #pragma unroll
    for (int o = 16; o; o >>= 1) {
        s  += __shfl_xor_sync(0xffffffffu, s,  o);
        ss += __shfl_xor_sync(0xffffffffu, ss, o);
    }
    __shared__ float red0[16], red1[16];
    __shared__ float stats[2];
    int w = t >> 5, ln = t & 31;
    if (ln == 0) { red0[w] = s; red1[w] = ss; }
    __syncthreads();
    if (t < 32) {
        float a  = (t < 16) ? red0[t] : 0.f;
        float b2 = (t < 16) ? red1[t] : 0.f;
        #pragma unroll
        for (int o = 8; o; o >>= 1) {
            a  += __shfl_xor_sync(0xffffffffu, a,  o);
            b2 += __shfl_xor_sync(0xffffffffu, b2, o);
        }
        if (t == 0) {
            float m   = a * (1.f / 8192.f);
            float var = b2 * (1.f / 8192.f) - m * m;
            stats[0] = m;
            stats[1] = rsqrtf(var + 1e-5f);
        }
    }
    __syncthreads();
    float m = stats[0];
    float gsc = gamma[j] * stats[1];
    float bt = beta[j];
    float d = has_skip ? dvec[j] : 0.f;
    const float* sb = has_skip ? (getbuf(skip_sel) + (size_t)j * 16) : nullptr;
    float* ob = getbuf(out_sel) + (size_t)j * 16;

    #pragma unroll
    for (int r = 0; r < 16; r++) {
        int e = r * 512 + t;
        int c = e >> 4, lane = e & 15;
        size_t off = (size_t)c * S16 + lane;
        float y = tanhf((v[r] - m) * gsc + bt);
        if (has_skip) y += sb[off] * d;
        ob[off] = y;
    }
}

// ---------------- output head: out[b] = b_out + sum_j h[b][j]*fasm[j]*w_out[j]
__global__ __launch_bounds__(512)
void out_kernel(int in_sel, const float* __restrict__ fasm,
                const float* __restrict__ wout, const float* __restrict__ bout,
                float* __restrict__ out) {
    __shared__ float fw[S];
    for (int i = threadIdx.x; i < S; i += blockDim.x) fw[i] = fasm[i] * wout[i];
    __syncthreads();
    int b = blockIdx.x * blockDim.x + threadIdx.x;   // 16 blocks x 512 = 8192
    int c = b >> 4, lane = b & 15;
    const float* base = getbuf(in_sel) + (size_t)c * S16 + lane;
    float s = *bout;
    for (int jj = 0; jj < S; jj++) {
        float f = fw[jj];
        if (f != 0.f) s += base[(size_t)jj * 16] * f;
    }
    out[b] = s;
}

// ---------------- launch ------------------------------------------------------
extern "C" void kernel_launch(void* const* d_in, const int* in_sizes, int n_in,
                              void* d_out, int out_size) {
    const float* x     = (const float*)d_in[0];
    const float* lm0   = (const float*)d_in[1];
    const float* lm    = (const float*)d_in[2];
    const float* flm   = (const float*)d_in[3];
    const float* fasm  = (const float*)d_in[4];
    const float* W0    = (const float*)d_in[5];
    const float* b0    = (const float*)d_in[6];
    const float* W     = (const float*)d_in[7];
    const float* bv    = (const float*)d_in[8];
    const float* gamma = (const float*)d_in[9];
    const float* beta  = (const float*)d_in[10];
    const float* wout  = (const float*)d_in[11];
    const float* bout  = (const float*)d_in[12];
    float* out = (float*)d_out;

    cudaFuncSetAttribute(spmm_kernel, cudaFuncAttributeMaxDynamicSharedMemorySize,
                         S * XS_STRIDE * 4);

    // 1) build sparse structure for all 7 layers (deterministic row order)
    build_kernel<<<dim3((S + 127) / 128, NLAY), 128>>>(lm0, W0, lm, W);

    // 2) tile/transpose x into bufA
    int tot = NC * G * 16;
    xt_kernel<<<(tot + 255) / 256, 256>>>(x);

    // 3) layer 0: sparse matmul (689 in-slots) -> bufB, then BN+tanh -> bufC
    spmm_kernel<<<NC, 1024, G * XS_STRIDE * 4>>>(0 /*bufA*/, b0, 0, G);
    bn_kernel<<<S, 512>>>(-1, 2 /*bufC*/, gamma, beta, nullptr, 0);

    // 4) layers 1..6
    int cur = 2, alt = 0;
    for (int l = 1; l <= 6; l++) {
        spmm_kernel<<<NC, 1024, S * XS_STRIDE * 4>>>(cur, bv + (size_t)(l - 1) * S, l, S);
        bn_kernel<<<S, 512>>>(cur, alt, gamma + (size_t)l * S, beta + (size_t)l * S,
                              flm + (size_t)(l - 1) * S, 1);
        int tmp = cur; cur = alt; alt = tmp;
    }

    // 5) output head
    out_kernel<<<16, 512>>>(cur, fasm, wout, bout, out);
}

// round 2
// speedup vs baseline: 1.7990x; 1.7990x over previous
#include <cuda_runtime.h>

// Problem constants
#define S      2785
#define S16    (S * 16)
#define G      689
#define BATCH  8192
#define NC     512            // batch chunks of 16
#define CAP    192            // max nnz per output column (binom mean ~56, 5-sigma ~93)
#define NLAY   7              // layer 0 + 6 scan layers
#define RSPLIT 8              // row-split factor for build
#define NGRID  444            // spmm grid (first 68 CTAs take 2 chunks: 444+68=512)
#define CUT    68

// ---------------- device global scratch (allocation-free rule) ----------------
__device__ float g_bufA[(size_t)NC * S16];
__device__ float g_bufB[(size_t)NC * S16];   // pre-BN Y, always
__device__ float g_bufC[(size_t)NC * S16];
__device__ int2  g_ent[(size_t)NLAY * S * CAP]; // {byte_offset = i*64, w-bits}
__device__ int   g_cnt[NLAY * S];               // even, <= CAP
__device__ int   g_cnt8[NLAY * RSPLIT * S];
__device__ int   g_off8[NLAY * RSPLIT * S];

__device__ __forceinline__ float* getbuf(int s) {
    return s == 0 ? g_bufA : (s == 1 ? g_bufB : g_bufC);
}

// ---------------- build phase A: per-row-chunk nnz counts --------------------
__global__ void count_kernel(const float* __restrict__ lm0, const float* __restrict__ lm) {
    int l = blockIdx.y, r = blockIdx.z;
    int j = blockIdx.x * 128 + threadIdx.x;
    if (j >= S) return;
    int rows = (l == 0) ? G : S;
    const float* M = (l == 0) ? lm0 : lm + (size_t)(l - 1) * S * S;
    int chunk = (rows + RSPLIT - 1) / RSPLIT;
    int i0 = r * chunk;
    int i1 = min(rows, i0 + chunk);
    int c = 0;
    #pragma unroll 8
    for (int i = i0; i < i1; i++)
        c += (M[(size_t)i * S + j] != 0.f);
    g_cnt8[(l * RSPLIT + r) * S + j] = c;
}

// ---------------- build phase B: prefix offsets + even padding ---------------
__global__ void prefix_kernel() {
    int l = blockIdx.y;
    int j = blockIdx.x * 128 + threadIdx.x;
    if (j >= S) return;
    int off = 0;
    #pragma unroll
    for (int r = 0; r < RSPLIT; r++) {
        int c = g_cnt8[(l * RSPLIT + r) * S + j];
        g_off8[(l * RSPLIT + r) * S + j] = off;
        off += c;
    }
    if (off > CAP) off = CAP;
    int2* ep = g_ent + ((size_t)l * S + j) * CAP;
    if (off & 1) { ep[off] = make_int2(0, 0); off++; }  // zero-weight pad entry
    g_cnt[l * S + j] = off;
}

// ---------------- build phase C: fill entries (row order preserved) ----------
__global__ void fill_kernel(const float* __restrict__ lm0, const float* __restrict__ W0,
                            const float* __restrict__ lm,  const float* __restrict__ Wl) {
    int l = blockIdx.y, r = blockIdx.z;
    int j = blockIdx.x * 128 + threadIdx.x;
    if (j >= S) return;
    int rows; const float* M; const float* Wm;
    if (l == 0) { rows = G; M = lm0; Wm = W0; }
    else {
        size_t off0 = (size_t)(l - 1) * S * S;
        rows = S; M = lm + off0; Wm = Wl + off0;
    }
    int chunk = (rows + RSPLIT - 1) / RSPLIT;
    int i0 = r * chunk;
    int i1 = min(rows, i0 + chunk);
    int o = g_off8[(l * RSPLIT + r) * S + j];
    int2* ep = g_ent + ((size_t)l * S + j) * CAP;
    #pragma unroll 4
    for (int i = i0; i < i1; i++) {
        float m = M[(size_t)i * S + j];
        if (m != 0.f) {
            if (o < CAP) {
                float w = Wm[(size_t)i * S + j];
                ep[o] = make_int2(i * 64, __float_as_int(w));  // 64B per slot (16 floats)
            }
            o++;
        }
    }
}

// ---------------- coalesced transpose x [B,G] -> [NC][G][16] into bufA -------
#define XT_TI 128
__global__ __launch_bounds__(256)
void xt_kernel(const float* __restrict__ x) {
    __shared__ float tile[16][XT_TI + 1];
    int c  = blockIdx.y;
    int i0 = blockIdx.x * XT_TI;
    int t  = threadIdx.x;
    int col = t & 127;
    // load 16 rows x 128 cols, coalesced 512B per row segment
    #pragma unroll
    for (int rr = 0; rr < 8; rr++) {
        int row = rr * 2 + (t >> 7);
        int i = i0 + col;
        tile[row][col] = (i < G) ? x[(size_t)(c * 16 + row) * G + i] : 0.f;
    }
    __syncthreads();
    // write [i][lane], fully coalesced 1KB stretches
    int lane = t & 15;
    #pragma unroll
    for (int b = 0; b < 8; b++) {
        int ii = (t >> 4) + b * 16;
        int i = i0 + ii;
        if (i < G)
            g_bufA[(size_t)c * (G * 16) + (size_t)i * 16 + lane] = tile[lane][ii];
    }
}

// ---------------- sparse SpMM: Y[c][j][0..15] = bias[j] + sum_k w * X[c][i_k][*]
__global__ __launch_bounds__(1024, 1)
void spmm_kernel(int in_sel, const float* __restrict__ bias, int layer, int n_slots) {
    extern __shared__ float xs[];
    const float* Xin = getbuf(in_sel);
    int npass = (blockIdx.x < CUT) ? 2 : 1;
    int lane4 = threadIdx.x & 3;
    int grp   = threadIdx.x >> 2;     // j-group 0..255
    const char* xsb = (const char*)xs + lane4 * 16;

    for (int p = 0; p < npass; p++) {
        int c = blockIdx.x + p * NGRID;
        if (p) __syncthreads();   // protect smem reuse across chunks

        // tile layout == gmem layout (stride 16 floats): straight float4 copy
        const float4* src = (const float4*)(Xin + (size_t)c * n_slots * 16);
        float4* dst = (float4*)xs;
        int n4 = n_slots * 4;
        for (int t = threadIdx.x; t < n4; t += 1024) dst[t] = src[t];
        __syncthreads();

        float* yb = g_bufB + (size_t)c * S16;
        for (int j = grp; j < S; j += 256) {
            int n2 = g_cnt[layer * S + j] >> 1;   // pairs
            const int4* ep = (const int4*)(g_ent + ((size_t)layer * S + j) * CAP);
            float bj = __ldg(bias + j);
            float4 acc = make_float4(bj, bj, bj, bj);
            #pragma unroll 2
            for (int k = 0; k < n2; k++) {
                int4 e = ep[k];                       // two entries per 16B load
                float4 x0 = *(const float4*)(xsb + e.x);
                float w0 = __int_as_float(e.y);
                float4 x1 = *(const float4*)(xsb + e.z);
                float w1 = __int_as_float(e.w);
                acc.x = fmaf(w0, x0.x, acc.x);
                acc.y = fmaf(w0, x0.y, acc.y);
                acc.z = fmaf(w0, x0.z, acc.z);
                acc.w = fmaf(w0, x0.w, acc.w);
                acc.x = fmaf(w1, x1.x, acc.x);
                acc.y = fmaf(w1, x1.y, acc.y);
                acc.z = fmaf(w1, x1.z, acc.z);
                acc.w = fmaf(w1, x1.w, acc.w);
            }
            *(float4*)(yb + j * 16 + lane4 * 4) = acc;
        }
    }
}

// ---------------- BatchNorm (training stats) + tanh + diagonal skip ----------
__global__ __launch_bounds__(512)
void bn_kernel(int skip_sel, int out_sel,
               const float* __restrict__ gamma, const float* __restrict__ beta,
               const float* __restrict__ dvec, int has_skip) {
    int j = blockIdx.x;
    int t = threadIdx.x;
    const float* base = g_bufB + (size_t)j * 16;

    float v[16];
    float s = 0.f, ss = 0.f;
    #pragma unroll
    for (int r = 0; r < 16; r++) {
        int e = r * 512 + t;
        int c = e >> 4, lane = e & 15;
        float xv = base[(size_t)c * S16 + lane];
        v[r] = xv; s += xv; ss += xv * xv;
    }
    #pragma unroll
    for (int o = 16; o; o >>= 1) {
        s  += __shfl_xor_sync(0xffffffffu, s,  o);
        ss += __shfl_xor_sync(0xffffffffu, ss, o);
    }
    __shared__ float red0[16], red1[16];
    __shared__ float stats[2];
    int w = t >> 5, ln = t & 31;
    if (ln == 0) { red0[w] = s; red1[w] = ss; }
    __syncthreads();
    if (t < 32) {
        float a  = (t < 16) ? red0[t] : 0.f;
        float b2 = (t < 16) ? red1[t] : 0.f;
        #pragma unroll
        for (int o = 8; o; o >>= 1) {
            a  += __shfl_xor_sync(0xffffffffu, a,  o);
            b2 += __shfl_xor_sync(0xffffffffu, b2, o);
        }
        if (t == 0) {
            float m   = a * (1.f / 8192.f);
            float var = b2 * (1.f / 8192.f) - m * m;
            stats[0] = m;
            stats[1] = rsqrtf(var + 1e-5f);
        }
    }
    __syncthreads();
    float m = stats[0];
    float gsc = gamma[j] * stats[1];
    float bt = beta[j];
    float d = has_skip ? dvec[j] : 0.f;
    const float* sb = has_skip ? (getbuf(skip_sel) + (size_t)j * 16) : nullptr;
    float* ob = getbuf(out_sel) + (size_t)j * 16;

    #pragma unroll
    for (int r = 0; r < 16; r++) {
        int e = r * 512 + t;
        int c = e >> 4, lane = e & 15;
        size_t off = (size_t)c * S16 + lane;
        float y = tanhf((v[r] - m) * gsc + bt);
        if (has_skip) y += sb[off] * d;
        ob[off] = y;
    }
}

// ---------------- output head ------------------------------------------------
__global__ __launch_bounds__(512)
void out_kernel(int in_sel, const float* __restrict__ fasm,
                const float* __restrict__ wout, const float* __restrict__ bout,
                float* __restrict__ out) {
    __shared__ float fw[S];
    for (int i = threadIdx.x; i < S; i += blockDim.x) fw[i] = fasm[i] * wout[i];
    __syncthreads();
    int b = blockIdx.x * blockDim.x + threadIdx.x;
    int c = b >> 4, lane = b & 15;
    const float* base = getbuf(in_sel) + (size_t)c * S16 + lane;
    float s = *bout;
    for (int jj = 0; jj < S; jj++) {
        float f = fw[jj];
        if (f != 0.f) s += base[(size_t)jj * 16] * f;
    }
    out[b] = s;
}

// ---------------- launch ------------------------------------------------------
extern "C" void kernel_launch(void* const* d_in, const int* in_sizes, int n_in,
                              void* d_out, int out_size) {
    const float* x     = (const float*)d_in[0];
    const float* lm0   = (const float*)d_in[1];
    const float* lm    = (const float*)d_in[2];
    const float* flm   = (const float*)d_in[3];
    const float* fasm  = (const float*)d_in[4];
    const float* W0    = (const float*)d_in[5];
    const float* b0    = (const float*)d_in[6];
    const float* W     = (const float*)d_in[7];
    const float* bv    = (const float*)d_in[8];
    const float* gamma = (const float*)d_in[9];
    const float* beta  = (const float*)d_in[10];
    const float* wout  = (const float*)d_in[11];
    const float* bout  = (const float*)d_in[12];
    float* out = (float*)d_out;

    cudaFuncSetAttribute(spmm_kernel, cudaFuncAttributeMaxDynamicSharedMemorySize,
                         S * 16 * 4);

    // 1) build sparse structure: count / prefix / fill (deterministic row order)
    count_kernel<<<dim3((S + 127) / 128, NLAY, RSPLIT), 128>>>(lm0, lm);
    prefix_kernel<<<dim3((S + 127) / 128, NLAY), 128>>>();
    fill_kernel<<<dim3((S + 127) / 128, NLAY, RSPLIT), 128>>>(lm0, W0, lm, W);

    // 2) coalesced tile/transpose x into bufA
    xt_kernel<<<dim3((G + XT_TI - 1) / XT_TI, NC), 256>>>(x);

    // 3) layer 0: sparse matmul (689 in-slots) -> bufB, then BN+tanh -> bufC
    spmm_kernel<<<NGRID, 1024, G * 16 * 4>>>(0 /*bufA*/, b0, 0, G);
    bn_kernel<<<S, 512>>>(-1, 2 /*bufC*/, gamma, beta, nullptr, 0);

    // 4) layers 1..6
    int cur = 2, alt = 0;
    for (int l = 1; l <= 6; l++) {
        spmm_kernel<<<NGRID, 1024, S * 16 * 4>>>(cur, bv + (size_t)(l - 1) * S, l, S);
        bn_kernel<<<S, 512>>>(cur, alt, gamma + (size_t)l * S, beta + (size_t)l * S,
                              flm + (size_t)(l - 1) * S, 1);
        int tmp = cur; cur = alt; alt = tmp;
    }

    // 5) output head
    out_kernel<<<16, 512>>>(cur, fasm, wout, bout, out);
}

// round 3
// speedup vs baseline: 1.9307x; 1.0732x over previous
#include <cuda_runtime.h>

// Problem constants
#define S      2785
#define S16    (S * 16)
#define G      689
#define NC     512            // batch chunks of 16
#define CAP    192            // max nnz per column (binom mean ~56, max ~90)
#define NLAY   7              // layer 0 + 6 scan layers
#define RSPLIT 8              // row-split factor for build
#define NB     349            // column blocks of 8 (349*8 = 2792 >= 2785)
#define NBP8   (NB * 8)
#define NGRID  444            // spmm grid; first 68 CTAs take 2 chunks (444+68=512)
#define CUT    68

// ---------------- device global scratch (allocation-free rule) ----------------
__device__ float g_bufA[(size_t)NC * S16];
__device__ float g_bufB[(size_t)NC * S16];   // pre-BN Y, always
__device__ float g_bufC[(size_t)NC * S16];
__device__ int2  g_be[(size_t)NLAY * NB * CAP * 8]; // blocked entries [l][b][k][g]
__device__ int   g_cnt[NLAY * S];               // raw nnz per column
__device__ int   g_cnt8[NLAY * RSPLIT * S];
__device__ int   g_off8[NLAY * RSPLIT * S];
__device__ int   g_perm[NLAY * NBP8];           // sorted column order (desc nnz)
__device__ int   g_scnt[NLAY * NBP8];           // nnz at sorted position
__device__ int   g_blkmax[NLAY * NB];           // max nnz in block = first of block

__device__ __forceinline__ float* getbuf(int s) {
    return s == 0 ? g_bufA : (s == 1 ? g_bufB : g_bufC);
}

// ---------------- build phase A: per-row-chunk nnz counts --------------------
__global__ void count_kernel(const float* __restrict__ lm0, const float* __restrict__ lm) {
    int l = blockIdx.y, r = blockIdx.z;
    int j = blockIdx.x * 128 + threadIdx.x;
    if (j >= S) return;
    int rows = (l == 0) ? G : S;
    const float* M = (l == 0) ? lm0 : lm + (size_t)(l - 1) * S * S;
    int chunk = (rows + RSPLIT - 1) / RSPLIT;
    int i0 = r * chunk;
    int i1 = min(rows, i0 + chunk);
    int c = 0;
    #pragma unroll 8
    for (int i = i0; i < i1; i++)
        c += (M[(size_t)i * S + j] != 0.f);
    g_cnt8[(l * RSPLIT + r) * S + j] = c;
}

// ---------------- build phase B: prefix offsets per column -------------------
__global__ void prefix_kernel() {
    int l = blockIdx.y;
    int j = blockIdx.x * 128 + threadIdx.x;
    if (j >= S) return;
    int off = 0;
    #pragma unroll
    for (int r = 0; r < RSPLIT; r++) {
        int c = g_cnt8[(l * RSPLIT + r) * S + j];
        g_off8[(l * RSPLIT + r) * S + j] = off;
        off += c;
    }
    g_cnt[l * S + j] = min(off, CAP);
}

// ---------------- build phase C: deterministic rank-sort (desc nnz, asc j) ---
__global__ __launch_bounds__(1024)
void sort_kernel() {
    int l = blockIdx.x;
    int t = threadIdx.x;
    __shared__ int scnt[S];
    __shared__ int ssort[NBP8];
    for (int p = t; p < NBP8; p += 1024) { g_perm[l * NBP8 + p] = -1; ssort[p] = 0; g_scnt[l * NBP8 + p] = 0; }
    for (int j = t; j < S; j += 1024) scnt[j] = g_cnt[l * S + j];
    __syncthreads();
    for (int j = t; j < S; j += 1024) {
        int c = scnt[j];
        int pos = 0;
        for (int j2 = 0; j2 < S; j2++) {
            int c2 = scnt[j2];
            pos += (c2 > c) || (c2 == c && j2 < j);
        }
        g_perm[l * NBP8 + pos] = j;
        g_scnt[l * NBP8 + pos] = c;
        ssort[pos] = c;
    }
    __syncthreads();
    for (int b = t; b < NB; b += 1024)
        g_blkmax[l * NB + b] = ssort[b * 8];   // descending order -> first is max
}

// ---------------- build phase D: zero-pad slots [cnt, blkmax) ----------------
__global__ void pad_kernel() {
    int l = blockIdx.y;
    int p = blockIdx.x * 256 + threadIdx.x;
    if (p >= NBP8) return;
    int b = p >> 3, g = p & 7;
    int c  = g_scnt[l * NBP8 + p];
    int km = g_blkmax[l * NB + b];
    int2* base = g_be + ((size_t)(l * NB + b) * CAP) * 8 + g;
    for (int k = c; k < km; k++) base[(size_t)k * 8] = make_int2(0, 0);
}

// ---------------- build phase E: fill entries (row order preserved) ----------
__global__ void fill_kernel(const float* __restrict__ lm0, const float* __restrict__ W0,
                            const float* __restrict__ lm,  const float* __restrict__ Wl) {
    int l = blockIdx.y, r = blockIdx.z;
    int p = blockIdx.x * 128 + threadIdx.x;
    if (p >= NBP8) return;
    int j = g_perm[l * NBP8 + p];
    if (j < 0) return;
    int b = p >> 3, g = p & 7;
    int rows; const float* M; const float* Wm;
    if (l == 0) { rows = G; M = lm0; Wm = W0; }
    else {
        size_t off0 = (size_t)(l - 1) * S * S;
        rows = S; M = lm + off0; Wm = Wl + off0;
    }
    int chunk = (rows + RSPLIT - 1) / RSPLIT;
    int i0 = r * chunk;
    int i1 = min(rows, i0 + chunk);
    int o = g_off8[(l * RSPLIT + r) * S + j];
    int2* base = g_be + ((size_t)(l * NB + b) * CAP) * 8 + g;
    #pragma unroll 4
    for (int i = i0; i < i1; i++) {
        float m = M[(size_t)i * S + j];
        if (m != 0.f) {
            if (o < CAP) {
                float w = Wm[(size_t)i * S + j];
                base[(size_t)o * 8] = make_int2(i * 64, __float_as_int(w));
            }
            o++;
        }
    }
}

// ---------------- coalesced transpose x [B,G] -> [NC][G][16] into bufA -------
#define XT_TI 128
__global__ __launch_bounds__(256)
void xt_kernel(const float* __restrict__ x) {
    __shared__ float tile[16][XT_TI + 1];
    int c  = blockIdx.y;
    int i0 = blockIdx.x * XT_TI;
    int t  = threadIdx.x;
    int col = t & 127;
    #pragma unroll
    for (int rr = 0; rr < 8; rr++) {
        int row = rr * 2 + (t >> 7);
        int i = i0 + col;
        tile[row][col] = (i < G) ? x[(size_t)(c * 16 + row) * G + i] : 0.f;
    }
    __syncthreads();
    int lane = t & 15;
    #pragma unroll
    for (int bq = 0; bq < 8; bq++) {
        int ii = (t >> 4) + bq * 16;
        int i = i0 + ii;
        if (i < G)
            g_bufA[(size_t)c * (G * 16) + (size_t)i * 16 + lane] = tile[lane][ii];
    }
}

// ---------------- sparse SpMM, blocked entries --------------------------------
__global__ __launch_bounds__(1024, 1)
void spmm_kernel(int in_sel, const float* __restrict__ bias, int layer, int n_slots) {
    extern __shared__ float xs[];
    const float* Xin = getbuf(in_sel);
    int npass = (blockIdx.x < CUT) ? 2 : 1;

    int w     = threadIdx.x >> 5;   // warp 0..31
    int lane  = threadIdx.x & 31;
    int g     = lane >> 2;          // column slot within block 0..7
    int lane4 = lane & 3;           // batch quarter
    const char* xsb = (const char*)xs + lane4 * 16;

    for (int p = 0; p < npass; p++) {
        int c = blockIdx.x + p * NGRID;
        if (p) __syncthreads();

        const float4* src = (const float4*)(Xin + (size_t)c * n_slots * 16);
        float4* dst = (float4*)xs;
        int n4 = n_slots * 4;
        for (int t = threadIdx.x; t < n4; t += 1024) dst[t] = src[t];
        __syncthreads();

        float* yb = g_bufB + (size_t)c * S16;
        for (int b = w; b < NB; b += 32) {
            int pp = b * 8 + g;
            int j  = g_perm[layer * NBP8 + pp];        // -1 for pad columns
            int km = g_blkmax[layer * NB + b];
            const int2* ep = g_be + ((size_t)(layer * NB + b) * CAP) * 8 + g;
            float bj = (j >= 0) ? __ldg(bias + j) : 0.f;
            float4 acc = make_float4(bj, bj, bj, bj);
            int k = 0;
            for (; k + 2 <= km; k += 2) {
                int2 e0 = ep[(size_t)k * 8];
                int2 e1 = ep[(size_t)k * 8 + 8];
                float4 x0 = *(const float4*)(xsb + e0.x);
                float4 x1 = *(const float4*)(xsb + e1.x);
                float w0 = __int_as_float(e0.y);
                float w1 = __int_as_float(e1.y);
                acc.x = fmaf(w0, x0.x, acc.x);
                acc.y = fmaf(w0, x0.y, acc.y);
                acc.z = fmaf(w0, x0.z, acc.z);
                acc.w = fmaf(w0, x0.w, acc.w);
                acc.x = fmaf(w1, x1.x, acc.x);
                acc.y = fmaf(w1, x1.y, acc.y);
                acc.z = fmaf(w1, x1.z, acc.z);
                acc.w = fmaf(w1, x1.w, acc.w);
            }
            if (k < km) {
                int2 e0 = ep[(size_t)k * 8];
                float4 x0 = *(const float4*)(xsb + e0.x);
                float w0 = __int_as_float(e0.y);
                acc.x = fmaf(w0, x0.x, acc.x);
                acc.y = fmaf(w0, x0.y, acc.y);
                acc.z = fmaf(w0, x0.z, acc.z);
                acc.w = fmaf(w0, x0.w, acc.w);
            }
            if (j >= 0) *(float4*)(yb + (size_t)j * 16 + lane4 * 4) = acc;
        }
    }
}

// ---------------- BatchNorm (training stats) + tanh + diagonal skip ----------
__global__ __launch_bounds__(512)
void bn_kernel(int skip_sel, int out_sel,
               const float* __restrict__ gamma, const float* __restrict__ beta,
               const float* __restrict__ dvec, int has_skip) {
    int j = blockIdx.x;
    int t = threadIdx.x;
    const float* base = g_bufB + (size_t)j * 16;

    float v[16];
    float s = 0.f, ss = 0.f;
    #pragma unroll
    for (int r = 0; r < 16; r++) {
        int e = r * 512 + t;
        int c = e >> 4, lane = e & 15;
        float xv = base[(size_t)c * S16 + lane];
        v[r] = xv; s += xv; ss += xv * xv;
    }
    #pragma unroll
    for (int o = 16; o; o >>= 1) {
        s  += __shfl_xor_sync(0xffffffffu, s,  o);
        ss += __shfl_xor_sync(0xffffffffu, ss, o);
    }
    __shared__ float red0[16], red1[16];
    __shared__ float stats[2];
    int w = t >> 5, ln = t & 31;
    if (ln == 0) { red0[w] = s; red1[w] = ss; }
    __syncthreads();
    if (t < 32) {
        float a  = (t < 16) ? red0[t] : 0.f;
        float b2 = (t < 16) ? red1[t] : 0.f;
        #pragma unroll
        for (int o = 8; o; o >>= 1) {
            a  += __shfl_xor_sync(0xffffffffu, a,  o);
            b2 += __shfl_xor_sync(0xffffffffu, b2, o);
        }
        if (t == 0) {
            float m   = a * (1.f / 8192.f);
            float var = b2 * (1.f / 8192.f) - m * m;
            stats[0] = m;
            stats[1] = rsqrtf(var + 1e-5f);
        }
    }
    __syncthreads();
    float m = stats[0];
    float gsc = gamma[j] * stats[1];
    float bt = beta[j];
    float d = has_skip ? dvec[j] : 0.f;
    const float* sb = has_skip ? (getbuf(skip_sel) + (size_t)j * 16) : nullptr;
    float* ob = getbuf(out_sel) + (size_t)j * 16;

    #pragma unroll
    for (int r = 0; r < 16; r++) {
        int e = r * 512 + t;
        int c = e >> 4, lane = e & 15;
        size_t off = (size_t)c * S16 + lane;
        float y = tanhf((v[r] - m) * gsc + bt);
        if (has_skip) y += sb[off] * d;
        ob[off] = y;
    }
}

// ---------------- output head ------------------------------------------------
__global__ __launch_bounds__(512)
void out_kernel(int in_sel, const float* __restrict__ fasm,
                const float* __restrict__ wout, const float* __restrict__ bout,
                float* __restrict__ out) {
    __shared__ float fw[S];
    for (int i = threadIdx.x; i < S; i += blockDim.x) fw[i] = fasm[i] * wout[i];
    __syncthreads();
    int b = blockIdx.x * blockDim.x + threadIdx.x;
    int c = b >> 4, lane = b & 15;
    const float* base = getbuf(in_sel) + (size_t)c * S16 + lane;
    float s = *bout;
    for (int jj = 0; jj < S; jj++) {
        float f = fw[jj];
        if (f != 0.f) s += base[(size_t)jj * 16] * f;
    }
    out[b] = s;
}

// ---------------- launch ------------------------------------------------------
extern "C" void kernel_launch(void* const* d_in, const int* in_sizes, int n_in,
                              void* d_out, int out_size) {
    const float* x     = (const float*)d_in[0];
    const float* lm0   = (const float*)d_in[1];
    const float* lm    = (const float*)d_in[2];
    const float* flm   = (const float*)d_in[3];
    const float* fasm  = (const float*)d_in[4];
    const float* W0    = (const float*)d_in[5];
    const float* b0    = (const float*)d_in[6];
    const float* W     = (const float*)d_in[7];
    const float* bv    = (const float*)d_in[8];
    const float* gamma = (const float*)d_in[9];
    const float* beta  = (const float*)d_in[10];
    const float* wout  = (const float*)d_in[11];
    const float* bout  = (const float*)d_in[12];
    float* out = (float*)d_out;

    cudaFuncSetAttribute(spmm_kernel, cudaFuncAttributeMaxDynamicSharedMemorySize,
                         S * 16 * 4);

    // 1) build sparse structure: count / prefix / sort / pad / fill
    count_kernel<<<dim3((S + 127) / 128, NLAY, RSPLIT), 128>>>(lm0, lm);
    prefix_kernel<<<dim3((S + 127) / 128, NLAY), 128>>>();
    sort_kernel<<<NLAY, 1024>>>();
    pad_kernel<<<dim3((NBP8 + 255) / 256, NLAY), 256>>>();
    fill_kernel<<<dim3((NBP8 + 127) / 128, NLAY, RSPLIT), 128>>>(lm0, W0, lm, W);

    // 2) coalesced tile/transpose x into bufA
    xt_kernel<<<dim3((G + XT_TI - 1) / XT_TI, NC), 256>>>(x);

    // 3) layer 0: sparse matmul (689 in-slots) -> bufB, then BN+tanh -> bufC
    spmm_kernel<<<NGRID, 1024, G * 16 * 4>>>(0 /*bufA*/, b0, 0, G);
    bn_kernel<<<S, 512>>>(-1, 2 /*bufC*/, gamma, beta, nullptr, 0);

    // 4) layers 1..6
    int cur = 2, alt = 0;
    for (int l = 1; l <= 6; l++) {
        spmm_kernel<<<NGRID, 1024, S * 16 * 4>>>(cur, bv + (size_t)(l - 1) * S, l, S);
        bn_kernel<<<S, 512>>>(cur, alt, gamma + (size_t)l * S, beta + (size_t)l * S,
                              flm + (size_t)(l - 1) * S, 1);
        int tmp = cur; cur = alt; alt = tmp;
    }

    // 5) output head
    out_kernel<<<16, 512>>>(cur, fasm, wout, bout, out);
}

// round 4
// speedup vs baseline: 2.3392x; 1.2116x over previous
#include <cuda_runtime.h>
#include <cuda_fp16.h>

// Problem constants
#define S      2785
#define S16    (S * 16)
#define G      689
#define NC     512            // batch chunks of 16
#define CAP    192            // max nnz per column (binom mean ~56, max ~90)
#define NLAY   7              // layer 0 + 6 scan layers
#define RSPLIT 8              // row-split factor for build
#define NB     349            // column blocks of 8 (349*8 = 2792 >= 2785)
#define NBP8   (NB * 8)
#define NGRID  444            // spmm grid; first 68 CTAs take 2 chunks (444+68=512)
#define CUT    68
#define SSTRIDE 48            // smem bytes per slot (24 halfs): spreads bank windows

// ---------------- device global scratch (allocation-free rule) ----------------
__device__ __half g_bufA[(size_t)NC * S16];   // activations fp16 (45.6 MB)
__device__ float  g_bufB[(size_t)NC * S16];   // pre-BN Y fp32 (91.3 MB)
__device__ __half g_bufC[(size_t)NC * S16];   // activations fp16
__device__ int2   g_be[(size_t)NLAY * NB * CAP * 8]; // blocked entries [l][b][k][g]
__device__ int    g_cnt[NLAY * S];
__device__ int    g_cnt8[NLAY * RSPLIT * S];
__device__ int    g_off8[NLAY * RSPLIT * S];
__device__ int    g_perm[NLAY * NBP8];        // sorted column order (desc nnz)
__device__ int    g_scnt[NLAY * NBP8];
__device__ int    g_blkmax[NLAY * NB];

__device__ __forceinline__ __half* getact(int s) { return s == 0 ? g_bufA : g_bufC; }

// ---------------- build phase A: per-row-chunk nnz counts --------------------
__global__ void count_kernel(const float* __restrict__ lm0, const float* __restrict__ lm) {
    int l = blockIdx.y, r = blockIdx.z;
    int j = blockIdx.x * 128 + threadIdx.x;
    if (j >= S) return;
    int rows = (l == 0) ? G : S;
    const float* M = (l == 0) ? lm0 : lm + (size_t)(l - 1) * S * S;
    int chunk = (rows + RSPLIT - 1) / RSPLIT;
    int i0 = r * chunk;
    int i1 = min(rows, i0 + chunk);
    int c = 0;
    #pragma unroll 8
    for (int i = i0; i < i1; i++)
        c += (M[(size_t)i * S + j] != 0.f);
    g_cnt8[(l * RSPLIT + r) * S + j] = c;
}

// ---------------- build phase B: prefix offsets per column -------------------
__global__ void prefix_kernel() {
    int l = blockIdx.y;
    int j = blockIdx.x * 128 + threadIdx.x;
    if (j >= S) return;
    int off = 0;
    #pragma unroll
    for (int r = 0; r < RSPLIT; r++) {
        int c = g_cnt8[(l * RSPLIT + r) * S + j];
        g_off8[(l * RSPLIT + r) * S + j] = off;
        off += c;
    }
    g_cnt[l * S + j] = min(off, CAP);
}

// ---------------- build phase C: deterministic rank-sort (desc nnz, asc j) ---
#define S4 ((S + 3) / 4)
__global__ __launch_bounds__(1024)
void sort_kernel() {
    int l = blockIdx.y;
    __shared__ int4 scnt4[S4];
    int* scnt = (int*)scnt4;
    for (int j = threadIdx.x; j < S4 * 4; j += 1024)
        scnt[j] = (j < S) ? g_cnt[l * S + j] : -1;     // pad never counts
    __syncthreads();

    int j = blockIdx.x * 1024 + threadIdx.x;           // grid.x = 3
    if (j < S) {
        int c = scnt[j];
        int pos = 0;
        for (int q = 0; q < S4; q++) {
            int4 v = scnt4[q];                          // warp-uniform broadcast
            int b0 = 4 * q;
            pos += (v.x > c) || (v.x == c && b0 + 0 < j);
            pos += (v.y > c) || (v.y == c && b0 + 1 < j);
            pos += (v.z > c) || (v.z == c && b0 + 2 < j);
            pos += (v.w > c) || (v.w == c && b0 + 3 < j);
        }
        g_perm[l * NBP8 + pos] = j;
        g_scnt[l * NBP8 + pos] = c;
        if ((pos & 7) == 0) g_blkmax[l * NB + (pos >> 3)] = c;
    }
    if (blockIdx.x == 0)
        for (int p = S + threadIdx.x; p < NBP8; p += 1024) {
            g_perm[l * NBP8 + p] = -1;
            g_scnt[l * NBP8 + p] = 0;
        }
}

// ---------------- build phase D: zero-pad slots [cnt, blkmax) ----------------
__global__ void pad_kernel() {
    int l = blockIdx.y;
    int p = blockIdx.x * 256 + threadIdx.x;
    if (p >= NBP8) return;
    int b = p >> 3, g = p & 7;
    int c  = g_scnt[l * NBP8 + p];
    int km = g_blkmax[l * NB + b];
    int2* base = g_be + ((size_t)(l * NB + b) * CAP) * 8 + g;
    for (int k = c; k < km; k++) base[(size_t)k * 8] = make_int2(0, 0);
}

// ---------------- build phase E: fill entries (row order preserved) ----------
__global__ void fill_kernel(const float* __restrict__ lm0, const float* __restrict__ W0,
                            const float* __restrict__ lm,  const float* __restrict__ Wl) {
    int l = blockIdx.y, r = blockIdx.z;
    int p = blockIdx.x * 128 + threadIdx.x;
    if (p >= NBP8) return;
    int j = g_perm[l * NBP8 + p];
    if (j < 0) return;
    int b = p >> 3, g = p & 7;
    int rows; const float* M; const float* Wm;
    if (l == 0) { rows = G; M = lm0; Wm = W0; }
    else {
        size_t off0 = (size_t)(l - 1) * S * S;
        rows = S; M = lm + off0; Wm = Wl + off0;
    }
    int chunk = (rows + RSPLIT - 1) / RSPLIT;
    int i0 = r * chunk;
    int i1 = min(rows, i0 + chunk);
    int o = g_off8[(l * RSPLIT + r) * S + j];
    int2* base = g_be + ((size_t)(l * NB + b) * CAP) * 8 + g;
    #pragma unroll 4
    for (int i = i0; i < i1; i++) {
        float m = M[(size_t)i * S + j];
        if (m != 0.f) {
            if (o < CAP) {
                float w = Wm[(size_t)i * S + j];
                base[(size_t)o * 8] = make_int2(i * SSTRIDE, __float_as_int(w));
            }
            o++;
        }
    }
}

// ---------------- coalesced transpose x [B,G] -> [NC][G][16] fp16 ------------
#define XT_TI 128
__global__ __launch_bounds__(256)
void xt_kernel(const float* __restrict__ x) {
    __shared__ float tile[16][XT_TI + 1];
    int c  = blockIdx.y;
    int i0 = blockIdx.x * XT_TI;
    int t  = threadIdx.x;
    int col = t & 127;
    #pragma unroll
    for (int rr = 0; rr < 8; rr++) {
        int row = rr * 2 + (t >> 7);
        int i = i0 + col;
        tile[row][col] = (i < G) ? x[(size_t)(c * 16 + row) * G + i] : 0.f;
    }
    __syncthreads();
    int lane = t & 15;
    #pragma unroll
    for (int bq = 0; bq < 8; bq++) {
        int ii = (t >> 4) + bq * 16;
        int i = i0 + ii;
        if (i < G)
            g_bufA[(size_t)c * (G * 16) + (size_t)i * 16 + lane] =
                __float2half_rn(tile[lane][ii]);
    }
}

// ---------------- sparse SpMM, fp16 activations, blocked entries --------------
__global__ __launch_bounds__(1024, 1)
void spmm_kernel(int in_sel, const float* __restrict__ bias, int layer, int n_slots) {
    extern __shared__ char xs[];
    const __half* Xin = getact(in_sel);
    int npass = (blockIdx.x < CUT) ? 2 : 1;

    int w     = threadIdx.x >> 5;
    int lane  = threadIdx.x & 31;
    int g     = lane >> 2;          // column slot within block 0..7
    int lane4 = lane & 3;           // batch quarter (4 halfs = 8B)
    const char* xsb = xs + lane4 * 8;

    for (int p = 0; p < npass; p++) {
        int c = blockIdx.x + p * NGRID;
        if (p) __syncthreads();

        // copy [n_slots][16] halfs (32B/slot) -> smem at stride SSTRIDE
        const uint4* src = (const uint4*)(Xin + (size_t)c * n_slots * 16);
        int nq = n_slots * 2;
        for (int t = threadIdx.x; t < nq; t += 1024) {
            int slot = t >> 1, q = t & 1;
            *(uint4*)(xs + slot * SSTRIDE + q * 16) = src[t];
        }
        __syncthreads();

        float* yb = g_bufB + (size_t)c * S16;
        for (int b = w; b < NB; b += 32) {
            int pp = b * 8 + g;
            int j  = g_perm[layer * NBP8 + pp];
            int km = g_blkmax[layer * NB + b];
            const int2* ep = g_be + ((size_t)(layer * NB + b) * CAP) * 8 + g;
            float bj = (j >= 0) ? __ldg(bias + j) : 0.f;
            float4 acc = make_float4(bj, bj, bj, bj);
            int k = 0;
            for (; k + 2 <= km; k += 2) {
                int2 e0 = ep[(size_t)k * 8];
                int2 e1 = ep[(size_t)k * 8 + 8];
                uint2 r0 = *(const uint2*)(xsb + e0.x);
                uint2 r1 = *(const uint2*)(xsb + e1.x);
                float w0 = __int_as_float(e0.y);
                float w1 = __int_as_float(e1.y);
                float2 a0 = __half22float2(*(__half2*)&r0.x);
                float2 a1 = __half22float2(*(__half2*)&r0.y);
                float2 b0 = __half22float2(*(__half2*)&r1.x);
                float2 b1 = __half22float2(*(__half2*)&r1.y);
                acc.x = fmaf(w0, a0.x, acc.x);
                acc.y = fmaf(w0, a0.y, acc.y);
                acc.z = fmaf(w0, a1.x, acc.z);
                acc.w = fmaf(w0, a1.y, acc.w);
                acc.x = fmaf(w1, b0.x, acc.x);
                acc.y = fmaf(w1, b0.y, acc.y);
                acc.z = fmaf(w1, b1.x, acc.z);
                acc.w = fmaf(w1, b1.y, acc.w);
            }
            if (k < km) {
                int2 e0 = ep[(size_t)k * 8];
                uint2 r0 = *(const uint2*)(xsb + e0.x);
                float w0 = __int_as_float(e0.y);
                float2 a0 = __half22float2(*(__half2*)&r0.x);
                float2 a1 = __half22float2(*(__half2*)&r0.y);
                acc.x = fmaf(w0, a0.x, acc.x);
                acc.y = fmaf(w0, a0.y, acc.y);
                acc.z = fmaf(w0, a1.x, acc.z);
                acc.w = fmaf(w0, a1.y, acc.w);
            }
            if (j >= 0) *(float4*)(yb + (size_t)j * 16 + lane4 * 4) = acc;
        }
    }
}

// ---------------- BatchNorm (training stats) + tanh + diagonal skip ----------
__global__ __launch_bounds__(512)
void bn_kernel(int skip_sel, int out_sel,
               const float* __restrict__ gamma, const float* __restrict__ beta,
               const float* __restrict__ dvec, int has_skip) {
    int j = blockIdx.x;
    int t = threadIdx.x;
    const float* base = g_bufB + (size_t)j * 16;

    float v[16];
    float s = 0.f, ss = 0.f;
    #pragma unroll
    for (int r = 0; r < 16; r++) {
        int e = r * 512 + t;
        int c = e >> 4, lane = e & 15;
        float xv = base[(size_t)c * S16 + lane];
        v[r] = xv; s += xv; ss += xv * xv;
    }
    #pragma unroll
    for (int o = 16; o; o >>= 1) {
        s  += __shfl_xor_sync(0xffffffffu, s,  o);
        ss += __shfl_xor_sync(0xffffffffu, ss, o);
    }
    __shared__ float red0[16], red1[16];
    __shared__ float stats[2];
    int w = t >> 5, ln = t & 31;
    if (ln == 0) { red0[w] = s; red1[w] = ss; }
    __syncthreads();
    if (t < 32) {
        float a  = (t < 16) ? red0[t] : 0.f;
        float b2 = (t < 16) ? red1[t] : 0.f;
        #pragma unroll
        for (int o = 8; o; o >>= 1) {
            a  += __shfl_xor_sync(0xffffffffu, a,  o);
            b2 += __shfl_xor_sync(0xffffffffu, b2, o);
        }
        if (t == 0) {
            float m   = a * (1.f / 8192.f);
            float var = b2 * (1.f / 8192.f) - m * m;
            stats[0] = m;
            stats[1] = rsqrtf(var + 1e-5f);
        }
    }
    __syncthreads();
    float m = stats[0];
    float gsc = gamma[j] * stats[1];
    float bt = beta[j];
    float d = has_skip ? dvec[j] : 0.f;
    const __half* sb = has_skip ? (getact(skip_sel) + (size_t)j * 16) : nullptr;
    __half* ob = getact(out_sel) + (size_t)j * 16;

    #pragma unroll
    for (int r = 0; r < 16; r++) {
        int e = r * 512 + t;
        int c = e >> 4, lane = e & 15;
        size_t off = (size_t)c * S16 + lane;
        float y = tanhf((v[r] - m) * gsc + bt);
        if (has_skip) y += __half2float(sb[off]) * d;
        ob[off] = __float2half_rn(y);
    }
}

// ---------------- output head ------------------------------------------------
__global__ __launch_bounds__(512)
void out_kernel(int in_sel, const float* __restrict__ fasm,
                const float* __restrict__ wout, const float* __restrict__ bout,
                float* __restrict__ out) {
    __shared__ float fw[S];
    for (int i = threadIdx.x; i < S; i += blockDim.x) fw[i] = fasm[i] * wout[i];
    __syncthreads();
    int b = blockIdx.x * blockDim.x + threadIdx.x;
    int c = b >> 4, lane = b & 15;
    const __half* base = getact(in_sel) + (size_t)c * S16 + lane;
    float s = *bout;
    for (int jj = 0; jj < S; jj++) {
        float f = fw[jj];
        if (f != 0.f) s += __half2float(base[(size_t)jj * 16]) * f;
    }
    out[b] = s;
}

// ---------------- launch ------------------------------------------------------
extern "C" void kernel_launch(void* const* d_in, const int* in_sizes, int n_in,
                              void* d_out, int out_size) {
    const float* x     = (const float*)d_in[0];
    const float* lm0   = (const float*)d_in[1];
    const float* lm    = (const float*)d_in[2];
    const float* flm   = (const float*)d_in[3];
    const float* fasm  = (const float*)d_in[4];
    const float* W0    = (const float*)d_in[5];
    const float* b0    = (const float*)d_in[6];
    const float* W     = (const float*)d_in[7];
    const float* bv    = (const float*)d_in[8];
    const float* gamma = (const float*)d_in[9];
    const float* beta  = (const float*)d_in[10];
    const float* wout  = (const float*)d_in[11];
    const float* bout  = (const float*)d_in[12];
    float* out = (float*)d_out;

    cudaFuncSetAttribute(spmm_kernel, cudaFuncAttributeMaxDynamicSharedMemorySize,
                         S * SSTRIDE);

    // 1) build sparse structure: count / prefix / sort / pad / fill
    count_kernel<<<dim3((S + 127) / 128, NLAY, RSPLIT), 128>>>(lm0, lm);
    prefix_kernel<<<dim3((S + 127) / 128, NLAY), 128>>>();
    sort_kernel<<<dim3((S + 1023) / 1024, NLAY), 1024>>>();
    pad_kernel<<<dim3((NBP8 + 255) / 256, NLAY), 256>>>();
    fill_kernel<<<dim3((NBP8 + 127) / 128, NLAY, RSPLIT), 128>>>(lm0, W0, lm, W);

    // 2) coalesced tile/transpose x into bufA (fp16)
    xt_kernel<<<dim3((G + XT_TI - 1) / XT_TI, NC), 256>>>(x);

    // 3) layer 0 -> bufB (fp32), BN+tanh -> bufC (fp16)
    spmm_kernel<<<NGRID, 1024, G * SSTRIDE>>>(0 /*bufA*/, b0, 0, G);
    bn_kernel<<<S, 512>>>(-1, 2 /*bufC*/, gamma, beta, nullptr, 0);

    // 4) layers 1..6
    int cur = 2, alt = 0;
    for (int l = 1; l <= 6; l++) {
        spmm_kernel<<<NGRID, 1024, S * SSTRIDE>>>(cur, bv + (size_t)(l - 1) * S, l, S);
        bn_kernel<<<S, 512>>>(cur, alt, gamma + (size_t)l * S, beta + (size_t)l * S,
                              flm + (size_t)(l - 1) * S, 1);
        int tmp = cur; cur = alt; alt = tmp;
    }

    // 5) output head
    out_kernel<<<16, 512>>>(cur, fasm, wout, bout, out);
}

// round 6
// speedup vs baseline: 2.7037x; 1.1558x over previous
#include <cuda_runtime.h>
#include <cuda_fp16.h>

// Problem constants
#define S      2785
#define S16    (S * 16)
#define G      689
#define NC     512            // batch chunks of 16
#define CAP    192            // max nnz per column
#define CAPP   (CAP / 2)      // entry pairs
#define NLAY   7
#define RSPLIT 8
#define NB     349            // column blocks of 8
#define NBP8   (NB * 8)
#define NGRID  444            // first 68 CTAs take 2 chunks (444+68=512)
#define CUT    68
#define SSTRIDE 48            // smem bytes per slot (24 halfs)

// ---------------- device global scratch ---------------------------------------
__device__ __half g_actA[(size_t)NC * S16];   // activations fp16 ping
__device__ __half g_actB[(size_t)NC * S16];   // activations fp16 pong
__device__ float  g_Y[(size_t)NC * S16];      // raw pre-BN layer output fp32
__device__ int4   g_be2[(size_t)NLAY * NB * CAPP * 8]; // paired entries [l][b][kp][g]
__device__ float2 g_part[(size_t)S * NC];     // per (j, chunk) {sum, sumsq}
__device__ float4 g_stat[S];                  // {mean, gamma*rstd, beta, d}
__device__ int    g_cnt[NLAY * S];
__device__ int    g_cnt8[NLAY * RSPLIT * S];
__device__ int    g_off8[NLAY * RSPLIT * S];
__device__ int    g_perm[NLAY * NBP8];
__device__ int    g_scnt[NLAY * NBP8];
__device__ int    g_blkmax[NLAY * NB];

__device__ __forceinline__ __half* getact(int s) { return s == 0 ? g_actA : g_actB; }

// ---------------- build phase A: per-row-chunk nnz counts --------------------
__global__ void count_kernel(const float* __restrict__ lm0, const float* __restrict__ lm) {
    int l = blockIdx.y, r = blockIdx.z;
    int j = blockIdx.x * 128 + threadIdx.x;
    if (j >= S) return;
    int rows = (l == 0) ? G : S;
    const float* M = (l == 0) ? lm0 : lm + (size_t)(l - 1) * S * S;
    int chunk = (rows + RSPLIT - 1) / RSPLIT;
    int i0 = r * chunk;
    int i1 = min(rows, i0 + chunk);
    int c = 0;
    #pragma unroll 8
    for (int i = i0; i < i1; i++)
        c += (M[(size_t)i * S + j] != 0.f);
    g_cnt8[(l * RSPLIT + r) * S + j] = c;
}

// ---------------- build phase B: prefix offsets per column -------------------
__global__ void prefix_kernel() {
    int l = blockIdx.y;
    int j = blockIdx.x * 128 + threadIdx.x;
    if (j >= S) return;
    int off = 0;
    #pragma unroll
    for (int r = 0; r < RSPLIT; r++) {
        int c = g_cnt8[(l * RSPLIT + r) * S + j];
        g_off8[(l * RSPLIT + r) * S + j] = off;
        off += c;
    }
    g_cnt[l * S + j] = min(off, CAP);
}

// ---------------- build phase C: deterministic rank-sort (desc nnz, asc j) ---
#define S4 ((S + 3) / 4)
__global__ __launch_bounds__(1024)
void sort_kernel() {
    int l = blockIdx.y;
    __shared__ int4 scnt4[S4];
    int* scnt = (int*)scnt4;
    for (int j = threadIdx.x; j < S4 * 4; j += 1024)
        scnt[j] = (j < S) ? g_cnt[l * S + j] : -1;
    __syncthreads();

    int j = blockIdx.x * 1024 + threadIdx.x;
    if (j < S) {
        int c = scnt[j];
        int pos = 0;
        for (int q = 0; q < S4; q++) {
            int4 v = scnt4[q];
            int b0 = 4 * q;
            pos += (v.x > c) || (v.x == c && b0 + 0 < j);
            pos += (v.y > c) || (v.y == c && b0 + 1 < j);
            pos += (v.z > c) || (v.z == c && b0 + 2 < j);
            pos += (v.w > c) || (v.w == c && b0 + 3 < j);
        }
        g_perm[l * NBP8 + pos] = j;
        g_scnt[l * NBP8 + pos] = c;
        if ((pos & 7) == 0) g_blkmax[l * NB + (pos >> 3)] = c;
    }
    if (blockIdx.x == 0)
        for (int p = S + threadIdx.x; p < NBP8; p += 1024) {
            g_perm[l * NBP8 + p] = -1;
            g_scnt[l * NBP8 + p] = 0;
        }
}

// ---------------- build phase D: zero-pad slots [cnt, 2*ceil(km/2)) ----------
__global__ void pad_kernel() {
    int l = blockIdx.y;
    int p = blockIdx.x * 256 + threadIdx.x;
    if (p >= NBP8) return;
    int b = p >> 3, g = p & 7;
    int c  = g_scnt[l * NBP8 + p];
    int km = g_blkmax[l * NB + b];
    int kmpad = ((km + 1) >> 1) << 1;
    int2* e2 = (int2*)g_be2;
    size_t bi = (size_t)(l * NB + b) * CAPP;
    for (int k = c; k < kmpad; k++)
        e2[((bi + (k >> 1)) * 8 + g) * 2 + (k & 1)] = make_int2(0, 0);
}

// ---------------- build phase E: fill entries (row order preserved) ----------
__global__ void fill_kernel(const float* __restrict__ lm0, const float* __restrict__ W0,
                            const float* __restrict__ lm,  const float* __restrict__ Wl) {
    int l = blockIdx.y, r = blockIdx.z;
    int p = blockIdx.x * 128 + threadIdx.x;
    if (p >= NBP8) return;
    int j = g_perm[l * NBP8 + p];
    if (j < 0) return;
    int b = p >> 3, g = p & 7;
    int rows; const float* M; const float* Wm;
    if (l == 0) { rows = G; M = lm0; Wm = W0; }
    else {
        size_t off0 = (size_t)(l - 1) * S * S;
        rows = S; M = lm + off0; Wm = Wl + off0;
    }
    int chunk = (rows + RSPLIT - 1) / RSPLIT;
    int i0 = r * chunk;
    int i1 = min(rows, i0 + chunk);
    int o = g_off8[(l * RSPLIT + r) * S + j];
    int2* e2 = (int2*)g_be2;
    size_t bi = (size_t)(l * NB + b) * CAPP;
    #pragma unroll 4
    for (int i = i0; i < i1; i++) {
        float m = M[(size_t)i * S + j];
        if (m != 0.f) {
            if (o < CAP) {
                float w = Wm[(size_t)i * S + j];
                e2[((bi + (o >> 1)) * 8 + g) * 2 + (o & 1)] =
                    make_int2(i * SSTRIDE, __float_as_int(w));
            }
            o++;
        }
    }
}

// ---------------- coalesced transpose x [B,G] -> [NC][G][16] fp16 ------------
#define XT_TI 128
__global__ __launch_bounds__(256)
void xt_kernel(const float* __restrict__ x) {
    __shared__ float tile[16][XT_TI + 1];
    int c  = blockIdx.y;
    int i0 = blockIdx.x * XT_TI;
    int t  = threadIdx.x;
    int col = t & 127;
    #pragma unroll
    for (int rr = 0; rr < 8; rr++) {
        int row = rr * 2 + (t >> 7);
        int i = i0 + col;
        tile[row][col] = (i < G) ? x[(size_t)(c * 16 + row) * G + i] : 0.f;
    }
    __syncthreads();
    int lane = t & 15;
    #pragma unroll
    for (int bq = 0; bq < 8; bq++) {
        int ii = (t >> 4) + bq * 16;
        int i = i0 + ii;
        if (i < G)
            g_actA[(size_t)c * (G * 16) + (size_t)i * 16 + lane] =
                __float2half_rn(tile[lane][ii]);
    }
}

// ---------------- fused SpMM: [BN+tanh+skip tile-load] + sparse gather + stats
// mode 0: plain fp16 tile load from actA (layer 0, n_slots=G)
// mode 1: fused: act = tanh((Y-m)*gs+bt) + skip*d; write act to wsel buffer
__global__ __launch_bounds__(1024, 1)
void spmm_kernel(int mode, int wsel, int ssel, int layer, int n_slots) {
    extern __shared__ char xs[];
    int npass = (blockIdx.x < CUT) ? 2 : 1;

    int w     = threadIdx.x >> 5;
    int lane  = threadIdx.x & 31;
    int g     = lane >> 2;
    int lane4 = lane & 3;
    const char* xsb = xs + lane4 * 8;

    for (int p = 0; p < npass; p++) {
        int c = blockIdx.x + p * NGRID;
        if (p) __syncthreads();

        if (mode == 0) {
            const uint4* src = (const uint4*)(g_actA + (size_t)c * n_slots * 16);
            int nq = n_slots * 2;
            for (int t = threadIdx.x; t < nq; t += 1024) {
                int slot = t >> 1, q = t & 1;
                *(uint4*)(xs + slot * SSTRIDE + q * 16) = src[t];
            }
        } else {
            const float* Yc = g_Y + (size_t)c * S16;
            const __half* skp = getact(ssel) + (size_t)c * S16;
            __half* actw = getact(wsel) + (size_t)c * S16;
            for (int q = threadIdx.x; q < S * 4; q += 1024) {
                int slot = q >> 2, quad = q & 3;
                float4 st = g_stat[slot];                 // {m, gs, bt, d}
                float4 y  = *(const float4*)(Yc + slot * 16 + quad * 4);
                uint2 sk  = *(const uint2*)(skp + slot * 16 + quad * 4);
                float2 s0 = __half22float2(*(__half2*)&sk.x);
                float2 s1 = __half22float2(*(__half2*)&sk.y);
                float a0 = tanhf((y.x - st.x) * st.y + st.z) + s0.x * st.w;
                float a1 = tanhf((y.y - st.x) * st.y + st.z) + s0.y * st.w;
                float a2 = tanhf((y.z - st.x) * st.y + st.z) + s1.x * st.w;
                float a3 = tanhf((y.w - st.x) * st.y + st.z) + s1.y * st.w;
                __half2 h0 = __floats2half2_rn(a0, a1);
                __half2 h1 = __floats2half2_rn(a2, a3);
                uint2 pk;
                *(__half2*)&pk.x = h0;
                *(__half2*)&pk.y = h1;
                *(uint2*)(xs + slot * SSTRIDE + quad * 8) = pk;
                *(uint2*)(actw + slot * 16 + quad * 4) = pk;
            }
        }
        __syncthreads();

        float* yb = g_Y + (size_t)c * S16;
        for (int b = w; b < NB; b += 32) {
            int pp = b * 8 + g;
            int j  = g_perm[layer * NBP8 + pp];
            int km = g_blkmax[layer * NB + b];
            int kmp = (km + 1) >> 1;
            const int4* ep4 = g_be2 + (size_t)(layer * NB + b) * CAPP * 8 + g;
            float4 acc = make_float4(0.f, 0.f, 0.f, 0.f);
            if (kmp > 0) {
                int4 e = ep4[0];
                for (int kp = 0; kp + 1 < kmp; kp++) {
                    int4 en = ep4[(size_t)(kp + 1) * 8];   // prefetch next pair
                    uint2 r0 = *(const uint2*)(xsb + e.x);
                    uint2 r1 = *(const uint2*)(xsb + e.z);
                    float w0 = __int_as_float(e.y);
                    float w1 = __int_as_float(e.w);
                    float2 a0 = __half22float2(*(__half2*)&r0.x);
                    float2 a1 = __half22float2(*(__half2*)&r0.y);
                    float2 b0 = __half22float2(*(__half2*)&r1.x);
                    float2 b1 = __half22float2(*(__half2*)&r1.y);
                    acc.x = fmaf(w0, a0.x, acc.x);
                    acc.y = fmaf(w0, a0.y, acc.y);
                    acc.z = fmaf(w0, a1.x, acc.z);
                    acc.w = fmaf(w0, a1.y, acc.w);
                    acc.x = fmaf(w1, b0.x, acc.x);
                    acc.y = fmaf(w1, b0.y, acc.y);
                    acc.z = fmaf(w1, b1.x, acc.z);
                    acc.w = fmaf(w1, b1.y, acc.w);
                    e = en;
                }
                {
                    uint2 r0 = *(const uint2*)(xsb + e.x);
                    uint2 r1 = *(const uint2*)(xsb + e.z);
                    float w0 = __int_as_float(e.y);
                    float w1 = __int_as_float(e.w);
                    float2 a0 = __half22float2(*(__half2*)&r0.x);
                    float2 a1 = __half22float2(*(__half2*)&r0.y);
                    float2 b0 = __half22float2(*(__half2*)&r1.x);
                    float2 b1 = __half22float2(*(__half2*)&r1.y);
                    acc.x = fmaf(w0, a0.x, acc.x);
                    acc.y = fmaf(w0, a0.y, acc.y);
                    acc.z = fmaf(w0, a1.x, acc.z);
                    acc.w = fmaf(w0, a1.y, acc.w);
                    acc.x = fmaf(w1, b0.x, acc.x);
                    acc.y = fmaf(w1, b0.y, acc.y);
                    acc.z = fmaf(w1, b1.x, acc.z);
                    acc.w = fmaf(w1, b1.y, acc.w);
                }
            }
            // BN partials: shuffles MUST run convergent (pad lanes j==-1 included;
            // their acc is 0 and they never store). R5 hang was these inside if(j>=0).
            float s  = acc.x + acc.y + acc.z + acc.w;
            float ss = acc.x * acc.x + acc.y * acc.y + acc.z * acc.z + acc.w * acc.w;
            s  += __shfl_xor_sync(0xffffffffu, s, 1);
            ss += __shfl_xor_sync(0xffffffffu, ss, 1);
            s  += __shfl_xor_sync(0xffffffffu, s, 2);
            ss += __shfl_xor_sync(0xffffffffu, ss, 2);
            if (j >= 0) {
                *(float4*)(yb + (size_t)j * 16 + lane4 * 4) = acc;
                if (lane4 == 0)
                    g_part[(size_t)j * NC + c] = make_float2(s, ss);
            }
        }
    }
}

// ---------------- stats: fold partials + gamma/beta/diag into float4 ---------
__global__ __launch_bounds__(256)
void stats_kernel(const float* __restrict__ gamma, const float* __restrict__ beta,
                  const float* __restrict__ dvec) {
    int j = blockIdx.x * 8 + (threadIdx.x >> 5);
    if (j >= S) return;
    int ln = threadIdx.x & 31;
    const float2* pt = g_part + (size_t)j * NC;
    float s = 0.f, ss = 0.f;
    #pragma unroll
    for (int i = 0; i < 16; i++) {
        float2 v = pt[ln + 32 * i];
        s += v.x; ss += v.y;
    }
    #pragma unroll
    for (int o = 16; o; o >>= 1) {
        s  += __shfl_xor_sync(0xffffffffu, s,  o);
        ss += __shfl_xor_sync(0xffffffffu, ss, o);
    }
    if (ln == 0) {
        float m   = s * (1.f / 8192.f);
        float var = ss * (1.f / 8192.f) - m * m;
        float rstd = rsqrtf(var + 1e-5f);
        g_stat[j] = make_float4(m, gamma[j] * rstd, beta[j],
                                dvec ? dvec[j] : 0.f);
    }
}

// ---------------- output head: applies layer-6 BN/tanh/skip inline -----------
__global__ __launch_bounds__(512)
void out_kernel(int ssel, const float* __restrict__ fasm,
                const float* __restrict__ wout, const float* __restrict__ bout,
                float* __restrict__ out) {
    __shared__ float fw[S];
    for (int i = threadIdx.x; i < S; i += blockDim.x) fw[i] = fasm[i] * wout[i];
    __syncthreads();
    int b = blockIdx.x * blockDim.x + threadIdx.x;
    int c = b >> 4, lane = b & 15;
    const float*  Yb = g_Y + (size_t)c * S16 + lane;
    const __half* sb = getact(ssel) + (size_t)c * S16 + lane;
    float s = *bout;
    for (int jj = 0; jj < S; jj++) {
        float f = fw[jj];
        if (f != 0.f) {
            float4 st = g_stat[jj];
            float y  = Yb[(size_t)jj * 16];
            float a5 = __half2float(sb[(size_t)jj * 16]);
            float a6 = tanhf((y - st.x) * st.y + st.z) + a5 * st.w;
            s += a6 * f;
        }
    }
    out[b] = s;
}

// ---------------- launch ------------------------------------------------------
extern "C" void kernel_launch(void* const* d_in, const int* in_sizes, int n_in,
                              void* d_out, int out_size) {
    const float* x     = (const float*)d_in[0];
    const float* lm0   = (const float*)d_in[1];
    const float* lm    = (const float*)d_in[2];
    const float* flm   = (const float*)d_in[3];
    const float* fasm  = (const float*)d_in[4];
    const float* W0    = (const float*)d_in[5];
    const float* W     = (const float*)d_in[7];
    const float* gamma = (const float*)d_in[9];
    const float* beta  = (const float*)d_in[10];
    const float* wout  = (const float*)d_in[11];
    const float* bout  = (const float*)d_in[12];
    float* out = (float*)d_out;
    // note: biases b0/b (d_in[6], d_in[8]) cancel exactly through training-mode BN

    cudaFuncSetAttribute(spmm_kernel, cudaFuncAttributeMaxDynamicSharedMemorySize,
                         S * SSTRIDE);

    // 1) build sparse structure
    count_kernel<<<dim3((S + 127) / 128, NLAY, RSPLIT), 128>>>(lm0, lm);
    prefix_kernel<<<dim3((S + 127) / 128, NLAY), 128>>>();
    sort_kernel<<<dim3((S + 1023) / 1024, NLAY), 1024>>>();
    pad_kernel<<<dim3((NBP8 + 255) / 256, NLAY), 256>>>();
    fill_kernel<<<dim3((NBP8 + 127) / 128, NLAY, RSPLIT), 128>>>(lm0, W0, lm, W);

    // 2) transpose x -> actA (fp16)
    xt_kernel<<<dim3((G + XT_TI - 1) / XT_TI, NC), 256>>>(x);

    // 3) layer 0: plain gather from actA -> Y0 + partials; stats0 (no skip)
    spmm_kernel<<<NGRID, 1024, G * SSTRIDE>>>(0, 0, 0, 0, G);
    stats_kernel<<<(S + 7) / 8, 256>>>(gamma, beta, nullptr);

    // 4) layers 1..6: fused BN/tanh/skip tile-load + gather; then stats_l
    for (int l = 1; l <= 6; l++) {
        int wsel = (l & 1) ? 1 : 0;   // h_{l-1} written to B for odd l
        int ssel = 1 - wsel;          // skip (h_{l-2}) read from the other
        spmm_kernel<<<NGRID, 1024, S * SSTRIDE>>>(1, wsel, ssel, l, S);
        stats_kernel<<<(S + 7) / 8, 256>>>(gamma + (size_t)l * S,
                                           beta + (size_t)l * S,
                                           flm + (size_t)(l - 1) * S);
    }

    // 5) output head (layer-6 activation computed inline; h_5 is in actA)
    out_kernel<<<16, 512>>>(0, fasm, wout, bout, out);
}

// round 7
// speedup vs baseline: 2.9431x; 1.0886x over previous
#include <cuda_runtime.h>
#include <cuda_fp16.h>

// Problem constants
#define S      2785
#define S16    (S * 16)
#define G      689
#define NC     512            // batch chunks of 16
#define CAP    192            // max nnz per column
#define CAPP   (CAP / 2)      // entry pairs
#define NLAY   7
#define RSPLIT 8
#define NB     349            // column blocks of 8
#define NBP8   (NB * 8)
#define NFULL  444            // CTAs 0..443: full chunks 0..443
#define NHALF  136            // CTAs 444..579: half-chunks of chunks 444..511
#define NGRID  (NFULL + NHALF)
#define SSTRIDE 48            // smem bytes per slot (24 halfs)

// ---------------- device global scratch ---------------------------------------
__device__ __half g_actA[(size_t)NC * S16];   // activations fp16 ping
__device__ __half g_actB[(size_t)NC * S16];   // activations fp16 pong
__device__ float  g_Y[(size_t)NC * S16];      // raw pre-BN layer output fp32
__device__ int4   g_be2[(size_t)NLAY * NB * CAPP * 8]; // paired entries [l][b][kp][g]
__device__ float2 g_part[(size_t)S * NC];     // per (j, chunk) {sum, sumsq}
__device__ float4 g_stat[S];                  // {mean, gamma*rstd, beta, d}
__device__ int    g_cnt[NLAY * S];
__device__ int    g_cnt8[NLAY * RSPLIT * S];
__device__ int    g_off8[NLAY * RSPLIT * S];
__device__ int    g_perm[NLAY * NBP8];
__device__ int    g_scnt[NLAY * NBP8];
__device__ int    g_blkmax[NLAY * NB];

__device__ __forceinline__ __half* getact(int s) { return s == 0 ? g_actA : g_actB; }

// ---------------- build phase A: per-row-chunk nnz counts --------------------
__global__ void count_kernel(const float* __restrict__ lm0, const float* __restrict__ lm) {
    int l = blockIdx.y, r = blockIdx.z;
    int j = blockIdx.x * 128 + threadIdx.x;
    if (j >= S) return;
    int rows = (l == 0) ? G : S;
    const float* M = (l == 0) ? lm0 : lm + (size_t)(l - 1) * S * S;
    int chunk = (rows + RSPLIT - 1) / RSPLIT;
    int i0 = r * chunk;
    int i1 = min(rows, i0 + chunk);
    int c = 0;
    #pragma unroll 8
    for (int i = i0; i < i1; i++)
        c += (M[(size_t)i * S + j] != 0.f);
    g_cnt8[(l * RSPLIT + r) * S + j] = c;
}

// ---------------- build phase B: prefix offsets per column -------------------
__global__ void prefix_kernel() {
    int l = blockIdx.y;
    int j = blockIdx.x * 128 + threadIdx.x;
    if (j >= S) return;
    int off = 0;
    #pragma unroll
    for (int r = 0; r < RSPLIT; r++) {
        int c = g_cnt8[(l * RSPLIT + r) * S + j];
        g_off8[(l * RSPLIT + r) * S + j] = off;
        off += c;
    }
    g_cnt[l * S + j] = min(off, CAP);
}

// ---------------- build phase C: deterministic rank-sort (desc nnz, asc j) ---
#define S4 ((S + 3) / 4)
__global__ __launch_bounds__(1024)
void sort_kernel() {
    int l = blockIdx.y;
    __shared__ int4 scnt4[S4];
    int* scnt = (int*)scnt4;
    for (int j = threadIdx.x; j < S4 * 4; j += 1024)
        scnt[j] = (j < S) ? g_cnt[l * S + j] : -1;
    __syncthreads();

    int j = blockIdx.x * 1024 + threadIdx.x;
    if (j < S) {
        int c = scnt[j];
        int pos = 0;
        for (int q = 0; q < S4; q++) {
            int4 v = scnt4[q];
            int b0 = 4 * q;
            pos += (v.x > c) || (v.x == c && b0 + 0 < j);
            pos += (v.y > c) || (v.y == c && b0 + 1 < j);
            pos += (v.z > c) || (v.z == c && b0 + 2 < j);
            pos += (v.w > c) || (v.w == c && b0 + 3 < j);
        }
        g_perm[l * NBP8 + pos] = j;
        g_scnt[l * NBP8 + pos] = c;
        if ((pos & 7) == 0) g_blkmax[l * NB + (pos >> 3)] = c;
    }
    if (blockIdx.x == 0)
        for (int p = S + threadIdx.x; p < NBP8; p += 1024) {
            g_perm[l * NBP8 + p] = -1;
            g_scnt[l * NBP8 + p] = 0;
        }
}

// ---------------- build phase D: zero-pad slots [cnt, 2*ceil(km/2)) ----------
__global__ void pad_kernel() {
    int l = blockIdx.y;
    int p = blockIdx.x * 256 + threadIdx.x;
    if (p >= NBP8) return;
    int b = p >> 3, g = p & 7;
    int c  = g_scnt[l * NBP8 + p];
    int km = g_blkmax[l * NB + b];
    int kmpad = ((km + 1) >> 1) << 1;
    int2* e2 = (int2*)g_be2;
    size_t bi = (size_t)(l * NB + b) * CAPP;
    for (int k = c; k < kmpad; k++)
        e2[((bi + (k >> 1)) * 8 + g) * 2 + (k & 1)] = make_int2(0, 0);
}

// ---------------- build phase E: fill entries (row order preserved) ----------
__global__ void fill_kernel(const float* __restrict__ lm0, const float* __restrict__ W0,
                            const float* __restrict__ lm,  const float* __restrict__ Wl) {
    int l = blockIdx.y, r = blockIdx.z;
    int p = blockIdx.x * 128 + threadIdx.x;
    if (p >= NBP8) return;
    int j = g_perm[l * NBP8 + p];
    if (j < 0) return;
    int b = p >> 3, g = p & 7;
    int rows; const float* M; const float* Wm;
    if (l == 0) { rows = G; M = lm0; Wm = W0; }
    else {
        size_t off0 = (size_t)(l - 1) * S * S;
        rows = S; M = lm + off0; Wm = Wl + off0;
    }
    int chunk = (rows + RSPLIT - 1) / RSPLIT;
    int i0 = r * chunk;
    int i1 = min(rows, i0 + chunk);
    int o = g_off8[(l * RSPLIT + r) * S + j];
    int2* e2 = (int2*)g_be2;
    size_t bi = (size_t)(l * NB + b) * CAPP;
    #pragma unroll 4
    for (int i = i0; i < i1; i++) {
        float m = M[(size_t)i * S + j];
        if (m != 0.f) {
            if (o < CAP) {
                float w = Wm[(size_t)i * S + j];
                e2[((bi + (o >> 1)) * 8 + g) * 2 + (o & 1)] =
                    make_int2(i * SSTRIDE, __float_as_int(w));
            }
            o++;
        }
    }
}

// ---------------- coalesced transpose x [B,G] -> [NC][G][16] fp16 ------------
#define XT_TI 128
__global__ __launch_bounds__(256)
void xt_kernel(const float* __restrict__ x) {
    __shared__ float tile[16][XT_TI + 1];
    int c  = blockIdx.y;
    int i0 = blockIdx.x * XT_TI;
    int t  = threadIdx.x;
    int col = t & 127;
    #pragma unroll
    for (int rr = 0; rr < 8; rr++) {
        int row = rr * 2 + (t >> 7);
        int i = i0 + col;
        tile[row][col] = (i < G) ? x[(size_t)(c * 16 + row) * G + i] : 0.f;
    }
    __syncthreads();
    int lane = t & 15;
    #pragma unroll
    for (int bq = 0; bq < 8; bq++) {
        int ii = (t >> 4) + bq * 16;
        int i = i0 + ii;
        if (i < G)
            g_actA[(size_t)c * (G * 16) + (size_t)i * 16 + lane] =
                __float2half_rn(tile[lane][ii]);
    }
}

// ---------------- fused SpMM: [BN+tanh+skip tile-load] + sparse gather + stats
// mode 0: plain fp16 tile load from actA (layer 0, n_slots=G)
// mode 1: fused: act = tanh((Y-m)*gs+bt) + skip*d; write act to wsel buffer
// Grid: 444 full-chunk CTAs + 136 half-chunk CTAs (interleaved block split).
__global__ __launch_bounds__(1024, 1)
void spmm_kernel(int mode, int wsel, int ssel, int layer, int n_slots) {
    extern __shared__ char xs[];

    int w     = threadIdx.x >> 5;
    int lane  = threadIdx.x & 31;
    int g     = lane >> 2;
    int lane4 = lane & 3;
    const char* xsb = xs + lane4 * 8;

    int bid = blockIdx.x;
    int c, b0, bstep;
    if (bid < NFULL) { c = bid; b0 = w; bstep = 32; }
    else {
        int t = bid - NFULL;
        c = NFULL + (t >> 1);
        b0 = (t & 1) + 2 * w;           // interleaved halves of sorted blocks
        bstep = 64;
    }

    if (mode == 0) {
        const uint4* src = (const uint4*)(g_actA + (size_t)c * n_slots * 16);
        int nq = n_slots * 2;
        for (int t = threadIdx.x; t < nq; t += 1024) {
            int slot = t >> 1, q = t & 1;
            *(uint4*)(xs + slot * SSTRIDE + q * 16) = src[t];
        }
    } else {
        const float* Yc = g_Y + (size_t)c * S16;
        const __half* skp = getact(ssel) + (size_t)c * S16;
        __half* actw = getact(wsel) + (size_t)c * S16;
        for (int q = threadIdx.x; q < S * 4; q += 1024) {
            int slot = q >> 2, quad = q & 3;
            float4 st = g_stat[slot];                 // {m, gs, bt, d}
            float4 y  = *(const float4*)(Yc + slot * 16 + quad * 4);
            uint2 sk  = *(const uint2*)(skp + slot * 16 + quad * 4);
            float2 s0 = __half22float2(*(__half2*)&sk.x);
            float2 s1 = __half22float2(*(__half2*)&sk.y);
            float a0 = tanhf((y.x - st.x) * st.y + st.z) + s0.x * st.w;
            float a1 = tanhf((y.y - st.x) * st.y + st.z) + s0.y * st.w;
            float a2 = tanhf((y.z - st.x) * st.y + st.z) + s1.x * st.w;
            float a3 = tanhf((y.w - st.x) * st.y + st.z) + s1.y * st.w;
            __half2 h0 = __floats2half2_rn(a0, a1);
            __half2 h1 = __floats2half2_rn(a2, a3);
            uint2 pk;
            *(__half2*)&pk.x = h0;
            *(__half2*)&pk.y = h1;
            *(uint2*)(xs + slot * SSTRIDE + quad * 8) = pk;
            *(uint2*)(actw + slot * 16 + quad * 4) = pk;  // dup writes on split chunks: identical bits
        }
    }
    __syncthreads();

    float* yb = g_Y + (size_t)c * S16;
    for (int b = b0; b < NB; b += bstep) {
        int pp = b * 8 + g;
        int j  = g_perm[layer * NBP8 + pp];
        int km = g_blkmax[layer * NB + b];
        int kmp = (km + 1) >> 1;
        const int4* ep4 = g_be2 + (size_t)(layer * NB + b) * CAPP * 8 + g;
        float4 acc = make_float4(0.f, 0.f, 0.f, 0.f);
        if (kmp > 0) {
            // software pipeline: gathers for pair k issued before FMAs of pair k-1
            int4 e = ep4[0];
            uint2 r0 = *(const uint2*)(xsb + e.x);
            uint2 r1 = *(const uint2*)(xsb + e.z);
            for (int kp = 0; kp + 1 < kmp; kp++) {
                int4 en = ep4[(size_t)(kp + 1) * 8];
                uint2 n0 = *(const uint2*)(xsb + en.x);
                uint2 n1 = *(const uint2*)(xsb + en.z);
                float w0 = __int_as_float(e.y);
                float w1 = __int_as_float(e.w);
                float2 a0 = __half22float2(*(__half2*)&r0.x);
                float2 a1 = __half22float2(*(__half2*)&r0.y);
                float2 b0v = __half22float2(*(__half2*)&r1.x);
                float2 b1v = __half22float2(*(__half2*)&r1.y);
                acc.x = fmaf(w0, a0.x, acc.x);
                acc.y = fmaf(w0, a0.y, acc.y);
                acc.z = fmaf(w0, a1.x, acc.z);
                acc.w = fmaf(w0, a1.y, acc.w);
                acc.x = fmaf(w1, b0v.x, acc.x);
                acc.y = fmaf(w1, b0v.y, acc.y);
                acc.z = fmaf(w1, b1v.x, acc.z);
                acc.w = fmaf(w1, b1v.y, acc.w);
                e = en; r0 = n0; r1 = n1;
            }
            {
                float w0 = __int_as_float(e.y);
                float w1 = __int_as_float(e.w);
                float2 a0 = __half22float2(*(__half2*)&r0.x);
                float2 a1 = __half22float2(*(__half2*)&r0.y);
                float2 b0v = __half22float2(*(__half2*)&r1.x);
                float2 b1v = __half22float2(*(__half2*)&r1.y);
                acc.x = fmaf(w0, a0.x, acc.x);
                acc.y = fmaf(w0, a0.y, acc.y);
                acc.z = fmaf(w0, a1.x, acc.z);
                acc.w = fmaf(w0, a1.y, acc.w);
                acc.x = fmaf(w1, b0v.x, acc.x);
                acc.y = fmaf(w1, b0v.y, acc.y);
                acc.z = fmaf(w1, b1v.x, acc.z);
                acc.w = fmaf(w1, b1v.y, acc.w);
            }
        }
        // BN partials: shuffles MUST run convergent (pad lanes j==-1 included).
        float s  = acc.x + acc.y + acc.z + acc.w;
        float ss = acc.x * acc.x + acc.y * acc.y + acc.z * acc.z + acc.w * acc.w;
        s  += __shfl_xor_sync(0xffffffffu, s, 1);
        ss += __shfl_xor_sync(0xffffffffu, ss, 1);
        s  += __shfl_xor_sync(0xffffffffu, s, 2);
        ss += __shfl_xor_sync(0xffffffffu, ss, 2);
        if (j >= 0) {
            *(float4*)(yb + (size_t)j * 16 + lane4 * 4) = acc;
            if (lane4 == 0)
                g_part[(size_t)j * NC + c] = make_float2(s, ss);
        }
    }
}

// ---------------- stats: fold partials + gamma/beta/diag into float4 ---------
__global__ __launch_bounds__(256)
void stats_kernel(const float* __restrict__ gamma, const float* __restrict__ beta,
                  const float* __restrict__ dvec) {
    int j = blockIdx.x * 8 + (threadIdx.x >> 5);
    if (j >= S) return;
    int ln = threadIdx.x & 31;
    const float2* pt = g_part + (size_t)j * NC;
    float s = 0.f, ss = 0.f;
    #pragma unroll
    for (int i = 0; i < 16; i++) {
        float2 v = pt[ln + 32 * i];
        s += v.x; ss += v.y;
    }
    #pragma unroll
    for (int o = 16; o; o >>= 1) {
        s  += __shfl_xor_sync(0xffffffffu, s,  o);
        ss += __shfl_xor_sync(0xffffffffu, ss, o);
    }
    if (ln == 0) {
        float m   = s * (1.f / 8192.f);
        float var = ss * (1.f / 8192.f) - m * m;
        float rstd = rsqrtf(var + 1e-5f);
        g_stat[j] = make_float4(m, gamma[j] * rstd, beta[j],
                                dvec ? dvec[j] : 0.f);
    }
}

// ---------------- output head: applies layer-6 BN/tanh/skip inline -----------
__global__ __launch_bounds__(512)
void out_kernel(int ssel, const float* __restrict__ fasm,
                const float* __restrict__ wout, const float* __restrict__ bout,
                float* __restrict__ out) {
    __shared__ float fw[S];
    for (int i = threadIdx.x; i < S; i += blockDim.x) fw[i] = fasm[i] * wout[i];
    __syncthreads();
    int b = blockIdx.x * blockDim.x + threadIdx.x;
    int c = b >> 4, lane = b & 15;
    const float*  Yb = g_Y + (size_t)c * S16 + lane;
    const __half* sb = getact(ssel) + (size_t)c * S16 + lane;
    float s = *bout;
    for (int jj = 0; jj < S; jj++) {
        float f = fw[jj];
        if (f != 0.f) {
            float4 st = g_stat[jj];
            float y  = Yb[(size_t)jj * 16];
            float a5 = __half2float(sb[(size_t)jj * 16]);
            float a6 = tanhf((y - st.x) * st.y + st.z) + a5 * st.w;
            s += a6 * f;
        }
    }
    out[b] = s;
}

// ---------------- launch ------------------------------------------------------
extern "C" void kernel_launch(void* const* d_in, const int* in_sizes, int n_in,
                              void* d_out, int out_size) {
    const float* x     = (const float*)d_in[0];
    const float* lm0   = (const float*)d_in[1];
    const float* lm    = (const float*)d_in[2];
    const float* flm   = (const float*)d_in[3];
    const float* fasm  = (const float*)d_in[4];
    const float* W0    = (const float*)d_in[5];
    const float* W     = (const float*)d_in[7];
    const float* gamma = (const float*)d_in[9];
    const float* beta  = (const float*)d_in[10];
    const float* wout  = (const float*)d_in[11];
    const float* bout  = (const float*)d_in[12];
    float* out = (float*)d_out;
    // note: biases b0/b (d_in[6], d_in[8]) cancel exactly through training-mode BN

    cudaFuncSetAttribute(spmm_kernel, cudaFuncAttributeMaxDynamicSharedMemorySize,
                         S * SSTRIDE);

    // 1) build sparse structure
    count_kernel<<<dim3((S + 127) / 128, NLAY, RSPLIT), 128>>>(lm0, lm);
    prefix_kernel<<<dim3((S + 127) / 128, NLAY), 128>>>();
    sort_kernel<<<dim3((S + 1023) / 1024, NLAY), 1024>>>();
    pad_kernel<<<dim3((NBP8 + 255) / 256, NLAY), 256>>>();
    fill_kernel<<<dim3((NBP8 + 127) / 128, NLAY, RSPLIT), 128>>>(lm0, W0, lm, W);

    // 2) transpose x -> actA (fp16)
    xt_kernel<<<dim3((G + XT_TI - 1) / XT_TI, NC), 256>>>(x);

    // 3) layer 0: plain gather from actA -> Y0 + partials; stats0 (no skip)
    spmm_kernel<<<NGRID, 1024, G * SSTRIDE>>>(0, 0, 0, 0, G);
    stats_kernel<<<(S + 7) / 8, 256>>>(gamma, beta, nullptr);

    // 4) layers 1..6: fused BN/tanh/skip tile-load + gather; then stats_l
    for (int l = 1; l <= 6; l++) {
        int wsel = (l & 1) ? 1 : 0;   // h_{l-1} written to B for odd l
        int ssel = 1 - wsel;          // skip (h_{l-2}) read from the other
        spmm_kernel<<<NGRID, 1024, S * SSTRIDE>>>(1, wsel, ssel, l, S);
        stats_kernel<<<(S + 7) / 8, 256>>>(gamma + (size_t)l * S,
                                           beta + (size_t)l * S,
                                           flm + (size_t)(l - 1) * S);
    }

    // 5) output head (layer-6 activation computed inline; h_5 is in actA)
    out_kernel<<<16, 512>>>(0, fasm, wout, bout, out);
}